// round 2
// baseline (speedup 1.0000x reference)
#include <cuda_runtime.h>

// Scratch for intermediate h3[256] and completion counter. __device__ globals: no allocation.
__device__ float g_h3[256];
__device__ unsigned int g_cnt = 0;

// Fused: 256 blocks x 128 threads, single wave (all resident: ~2KB smem, 128 thr).
// Each block redundantly builds h[2048] in shared (~7K FLOPs, free), computes one
// row of the 256x2048 GEMV, then block 0 spins for completion and runs the
// 6x256 epilogue. Counter is reset so the launch is graph-replayable.
__global__ void __launch_bounds__(128, 8) actor_fused(
    const float* __restrict__ x,
    const float* __restrict__ conv_w, const float* __restrict__ conv_b,
    const float* __restrict__ w0, const float* __restrict__ b0,
    const float* __restrict__ w1, const float* __restrict__ b1,
    const float* __restrict__ w2, const float* __restrict__ b2,
    const float* __restrict__ w3, const float* __restrict__ b3,
    const float* __restrict__ w4, const float* __restrict__ b4,
    float* __restrict__ out)
{
    __shared__ __align__(16) float h[2048];
    __shared__ float red[4];

    const int c = threadIdx.x;           // 0..127 = channel index
    const int row = blockIdx.x;

    // ---- issue the 4 w3 row loads EARLY (independent of h build) ----
    const float4* __restrict__ w3r = reinterpret_cast<const float4*>(w3 + (size_t)row * 2048);
    float4 wv0 = w3r[c];
    float4 wv1 = w3r[c + 128];
    float4 wv2 = w3r[c + 256];
    float4 wv3 = w3r[c + 384];

    // ---- build h (each thread owns channel c across all segments) ----
    const float x07 = x[0 * 8 + 7];
    const float x17 = x[1 * 8 + 7];
    const float x47 = x[4 * 8 + 7];

    float x2r[8], x3r[8], x4r[6];
#pragma unroll
    for (int i = 0; i < 8; i++) { x2r[i] = x[16 + i]; x3r[i] = x[24 + i]; }
#pragma unroll
    for (int i = 0; i < 6; i++) { x4r[i] = x[32 + i]; }

    float cw[4];
#pragma unroll
    for (int k = 0; k < 4; k++) cw[k] = conv_w[c * 4 + k];
    const float cb = conv_b[c];

    h[c]        = fmaxf(fmaf(w0[c], x07, b0[c]), 0.0f);            // s0: [0,128)
    h[128 + c]  = fmaxf(fmaf(w1[c], x17, b1[c]), 0.0f);            // s1: [128,256)

#pragma unroll
    for (int t = 0; t < 5; t++) {                                   // s2,s3: conv T=5
        float a2 = cb, a3 = cb;
#pragma unroll
        for (int k = 0; k < 4; k++) {
            a2 = fmaf(cw[k], x2r[t + k], a2);
            a3 = fmaf(cw[k], x3r[t + k], a3);
        }
        h[256 + c * 5 + t] = fmaxf(a2, 0.0f);                       // [256,896)
        h[896 + c * 5 + t] = fmaxf(a3, 0.0f);                       // [896,1536)
    }
#pragma unroll
    for (int t = 0; t < 3; t++) {                                   // s4: conv over x[4,:6], T=3
        float a4 = cb;
#pragma unroll
        for (int k = 0; k < 4; k++) a4 = fmaf(cw[k], x4r[t + k], a4);
        h[1536 + c * 3 + t] = fmaxf(a4, 0.0f);                      // [1536,1920)
    }
    h[1920 + c] = fmaf(w2[c], x47, b2[c]);                          // s5: NO relu, [1920,2048)

    __syncthreads();

    // ---- row dot: w3[row, :] . h ----
    const float4* __restrict__ h4 = reinterpret_cast<const float4*>(h);
    float4 hv0 = h4[c];
    float4 hv1 = h4[c + 128];
    float4 hv2 = h4[c + 256];
    float4 hv3 = h4[c + 384];

    float acc = 0.0f;
    acc = fmaf(wv0.x, hv0.x, acc); acc = fmaf(wv0.y, hv0.y, acc);
    acc = fmaf(wv0.z, hv0.z, acc); acc = fmaf(wv0.w, hv0.w, acc);
    acc = fmaf(wv1.x, hv1.x, acc); acc = fmaf(wv1.y, hv1.y, acc);
    acc = fmaf(wv1.z, hv1.z, acc); acc = fmaf(wv1.w, hv1.w, acc);
    acc = fmaf(wv2.x, hv2.x, acc); acc = fmaf(wv2.y, hv2.y, acc);
    acc = fmaf(wv2.z, hv2.z, acc); acc = fmaf(wv2.w, hv2.w, acc);
    acc = fmaf(wv3.x, hv3.x, acc); acc = fmaf(wv3.y, hv3.y, acc);
    acc = fmaf(wv3.z, hv3.z, acc); acc = fmaf(wv3.w, hv3.w, acc);

#pragma unroll
    for (int o = 16; o > 0; o >>= 1) acc += __shfl_xor_sync(0xffffffffu, acc, o);
    if ((c & 31) == 0) red[c >> 5] = acc;
    __syncthreads();

    if (c == 0) {
        float s = red[0] + red[1] + red[2] + red[3] + b3[row];
        g_h3[row] = fmaxf(s, 0.0f);
        __threadfence();
        atomicAdd(&g_cnt, 1u);
    }

    // ---- block 0: wait for all rows, then 6x256 epilogue ----
    if (row != 0) return;

    if (c == 0) {
        while (atomicAdd(&g_cnt, 0u) < 256u) { }
    }
    __syncthreads();
    __threadfence();

    const float hr0 = g_h3[c];
    const float hr1 = g_h3[c + 128];

    float a[6];
#pragma unroll
    for (int j = 0; j < 6; j++) {
        a[j] = fmaf(w4[j * 256 + c], hr0, w4[j * 256 + c + 128] * hr1);
    }
#pragma unroll
    for (int o = 16; o > 0; o >>= 1) {
#pragma unroll
        for (int j = 0; j < 6; j++) a[j] += __shfl_xor_sync(0xffffffffu, a[j], o);
    }

    __shared__ float red2[4][6];
    if ((c & 31) == 0) {
#pragma unroll
        for (int j = 0; j < 6; j++) red2[c >> 5][j] = a[j];
    }
    __syncthreads();
    if (c < 6) {
        out[c] = red2[0][c] + red2[1][c] + red2[2][c] + red2[3][c] + b4[c];
    }
    if (c == 6) {
        g_cnt = 0;   // reset for next graph replay (deterministic)
    }
}

extern "C" void kernel_launch(void* const* d_in, const int* in_sizes, int n_in,
                              void* d_out, int out_size)
{
    const float* x      = (const float*)d_in[0];
    const float* conv_w = (const float*)d_in[1];
    const float* conv_b = (const float*)d_in[2];
    const float* w0     = (const float*)d_in[3];
    const float* b0     = (const float*)d_in[4];
    const float* w1     = (const float*)d_in[5];
    const float* b1     = (const float*)d_in[6];
    const float* w2     = (const float*)d_in[7];
    const float* b2     = (const float*)d_in[8];
    const float* w3     = (const float*)d_in[9];
    const float* b3     = (const float*)d_in[10];
    const float* w4     = (const float*)d_in[11];
    const float* b4     = (const float*)d_in[12];
    float* out = (float*)d_out;

    actor_fused<<<256, 128>>>(x, conv_w, conv_b, w0, b0, w1, b1, w2, b2,
                              w3, b3, w4, b4, out);
}